// round 14
// baseline (speedup 1.0000x reference)
#include <cuda_runtime.h>
#include <cuda_bf16.h>
#include <cstdint>

// out[r] = W0 + b + sum_n x[r,n] * ( wlin[n] + D[r,n] ),
//   D[r,n] = sum_k x[r,k] * Q[k,n]   (Q upper-triangular)
// bf16 HMMA (m16n8k16), split precision: D = Xh*Bh + Xh*Bl + Xl*Bh.
//
// R14: warp tile halved to 16 rows (1 m16 tile, acc=32 regs), TPB=256,
// BM=128, grid=256, launch_bounds(256,2) -> 16 warps/SM to hide the
// ldsm->mma and LDG latencies that capped all previous tensor rounds.

#define DIMS 64
#define BM   128
#define TPB  256
#define NBLK 256
#define ASTR 144               // smem bytes per row (128B data + 16B pad)

#define SM_WLIN 0              // 64 fp32
#define SM_W0B  256
#define SM_AH   512
#define SM_AL   (SM_AH + BM * ASTR)
#define SM_BH   (SM_AL + BM * ASTR)
#define SM_BL   (SM_BH + DIMS * ASTR)
#define SM_TOTAL (SM_BL + DIMS * ASTR)

__device__ __forceinline__ uint32_t smem_u32(const void* p) {
    uint32_t a;
    asm("{ .reg .u64 t; cvta.to.shared.u64 t, %1; cvt.u32.u64 %0, t; }"
        : "=r"(a) : "l"(p));
    return a;
}
__device__ __forceinline__ void ldsm_x4(uint32_t& a0, uint32_t& a1,
                                        uint32_t& a2, uint32_t& a3, uint32_t addr) {
    asm volatile("ldmatrix.sync.aligned.m8n8.x4.shared.b16 {%0,%1,%2,%3}, [%4];"
                 : "=r"(a0), "=r"(a1), "=r"(a2), "=r"(a3) : "r"(addr));
}
__device__ __forceinline__ void ldsm_x2(uint32_t& b0, uint32_t& b1, uint32_t addr) {
    asm volatile("ldmatrix.sync.aligned.m8n8.x2.shared.b16 {%0,%1}, [%2];"
                 : "=r"(b0), "=r"(b1) : "r"(addr));
}
__device__ __forceinline__ void mma16816(float* c, uint32_t a0, uint32_t a1,
                                         uint32_t a2, uint32_t a3,
                                         uint32_t b0, uint32_t b1) {
    asm volatile(
        "mma.sync.aligned.m16n8k16.row.col.f32.bf16.bf16.f32 "
        "{%0,%1,%2,%3}, {%4,%5,%6,%7}, {%8,%9}, {%0,%1,%2,%3};"
        : "+f"(c[0]), "+f"(c[1]), "+f"(c[2]), "+f"(c[3])
        : "r"(a0), "r"(a1), "r"(a2), "r"(a3), "r"(b0), "r"(b1));
}

__global__ void __launch_bounds__(TPB, 2)
poly_model_kernel(const float* __restrict__ x,
                  const float* __restrict__ W,
                  const float* __restrict__ bias,
                  float* __restrict__ out)
{
    extern __shared__ char smem[];
    const uint32_t sb = smem_u32(smem);
    const int tid  = threadIdx.x;
    const int wid  = tid >> 5;
    const int lane = tid & 31;

    if (tid < DIMS)
        reinterpret_cast<float*>(smem + SM_WLIN)[tid] = W[1 + tid];
    if (tid == 0)
        *reinterpret_cast<float*>(smem + SM_W0B) = W[0] + bias[0];

    // ---- B tiles: B[n][k] = Q[k][n] (k<=n else 0), bf16 hi/lo ----
    #pragma unroll
    for (int it = 0; it < 16; it++) {
        const int idx = tid + it * TPB;          // 0..4095
        const int n = idx >> 6, k = idx & 63;
        float bv = 0.0f;
        if (k <= n) {
            const int base = 1 + DIMS + k * DIMS - (k * (k - 1)) / 2;
            bv = W[base + (n - k)];
        }
        const __nv_bfloat16 h = __float2bfloat16(bv);
        const __nv_bfloat16 l = __float2bfloat16(bv - __bfloat162float(h));
        const int off = n * ASTR + k * 2;
        *reinterpret_cast<__nv_bfloat16*>(smem + SM_BH + off) = h;
        *reinterpret_cast<__nv_bfloat16*>(smem + SM_BL + off) = l;
    }

    // ---- A tiles: coalesced fp32 LDG.128 -> split bf16 hi/lo -> smem ----
    const float4* xg = reinterpret_cast<const float4*>(x)
                     + (size_t)blockIdx.x * BM * (DIMS / 4);
    #pragma unroll
    for (int i = 0; i < 8; i++) {
        const int q    = tid + i * TPB;          // 0..2047
        const float4 v = xg[q];
        const int row  = q >> 4;
        const int c4   = q & 15;

        __nv_bfloat162 h01 = __floats2bfloat162_rn(v.x, v.y);
        __nv_bfloat162 h23 = __floats2bfloat162_rn(v.z, v.w);
        const float2 f01 = __bfloat1622float2(h01);
        const float2 f23 = __bfloat1622float2(h23);
        __nv_bfloat162 l01 = __floats2bfloat162_rn(v.x - f01.x, v.y - f01.y);
        __nv_bfloat162 l23 = __floats2bfloat162_rn(v.z - f23.x, v.w - f23.y);

        const int off = row * ASTR + c4 * 8;
        uint2 hh, ll;
        hh.x = *reinterpret_cast<uint32_t*>(&h01);
        hh.y = *reinterpret_cast<uint32_t*>(&h23);
        ll.x = *reinterpret_cast<uint32_t*>(&l01);
        ll.y = *reinterpret_cast<uint32_t*>(&l23);
        *reinterpret_cast<uint2*>(smem + SM_AH + off) = hh;
        *reinterpret_cast<uint2*>(smem + SM_AL + off) = ll;
    }
    __syncthreads();

    // ---- accumulators init with wlin (D_init[r,c] = wlin[c]) ----
    const float* wlin = reinterpret_cast<const float*>(smem + SM_WLIN);
    float acc[8][4];
    #pragma unroll
    for (int n = 0; n < 8; n++) {
        const float2 wl = *reinterpret_cast<const float2*>(
            &wlin[n * 8 + (lane & 3) * 2]);
        acc[n][0] = wl.x; acc[n][1] = wl.y;
        acc[n][2] = wl.x; acc[n][3] = wl.y;
    }

    // ---- warp MMA mainloop: warp owns 16 rows x 64 cols ----
    const uint32_t aLane = (uint32_t)((((lane >> 3) & 1) * 8 + (lane & 7)) * ASTR
                                      + (lane >> 4) * 16);
    const uint32_t bLane = (uint32_t)((lane & 7) * ASTR + ((lane >> 3) & 1) * 16);
    const uint32_t aRow0 = (uint32_t)(wid * 16) * ASTR;

    const uint32_t aBase[3] = { sb + SM_AH, sb + SM_AH, sb + SM_AL };
    const uint32_t bBase[3] = { sb + SM_BH, sb + SM_BL, sb + SM_BH };

    #pragma unroll
    for (int pass = 0; pass < 3; pass++) {
        const uint32_t ab = aBase[pass] + aRow0 + aLane;
        const uint32_t bb = bBase[pass] + bLane;
        #pragma unroll
        for (int k = 0; k < 4; k++) {
            const uint32_t kbyte = k * 32;
            uint32_t a0, a1, a2, a3;
            ldsm_x4(a0, a1, a2, a3, ab + kbyte);
            #pragma unroll
            for (int n = 0; n < 8; n++) {
                uint32_t b0, b1;
                ldsm_x2(b0, b1, bb + n * 8 * ASTR + kbyte);
                mma16816(acc[n], a0, a1, a2, a3, b0, b1);
            }
        }
    }

    // ---- epilogue: out[r] = sum_c x[c]*acc[c] + W0 + b ----
    const float w0b = *reinterpret_cast<const float*>(smem + SM_W0B);
    const int r0 = wid * 16 + (lane >> 2);
    const int r1 = r0 + 8;
    float p0 = 0.0f, p1 = 0.0f;
    #pragma unroll
    for (int n = 0; n < 8; n++) {
        const int c0 = n * 8 + (lane & 3) * 2;
        const int o0 = r0 * ASTR + c0 * 2;
        const int o1 = r1 * ASTR + c0 * 2;
        const float2 xh0 = __bfloat1622float2(
            *reinterpret_cast<const __nv_bfloat162*>(smem + SM_AH + o0));
        const float2 xl0 = __bfloat1622float2(
            *reinterpret_cast<const __nv_bfloat162*>(smem + SM_AL + o0));
        const float2 xh1 = __bfloat1622float2(
            *reinterpret_cast<const __nv_bfloat162*>(smem + SM_AH + o1));
        const float2 xl1 = __bfloat1622float2(
            *reinterpret_cast<const __nv_bfloat162*>(smem + SM_AL + o1));

        p0 = fmaf(xh0.x + xl0.x, acc[n][0], p0);
        p0 = fmaf(xh0.y + xl0.y, acc[n][1], p0);
        p1 = fmaf(xh1.x + xl1.x, acc[n][2], p1);
        p1 = fmaf(xh1.y + xl1.y, acc[n][3], p1);
    }
    p0 += __shfl_xor_sync(0xffffffffu, p0, 1);
    p0 += __shfl_xor_sync(0xffffffffu, p0, 2);
    p1 += __shfl_xor_sync(0xffffffffu, p1, 1);
    p1 += __shfl_xor_sync(0xffffffffu, p1, 2);
    if ((lane & 3) == 0) {
        const int gr = blockIdx.x * BM;
        out[gr + r0] = p0 + w0b;
        out[gr + r1] = p1 + w0b;
    }
}

extern "C" void kernel_launch(void* const* d_in, const int* in_sizes, int n_in,
                              void* d_out, int out_size)
{
    const float* x    = (const float*)d_in[0];  // [32768, 64]
    const float* W    = (const float*)d_in[1];  // [2145]
    const float* bias = (const float*)d_in[2];  // [1]
    float* out = (float*)d_out;                 // [32768]

    cudaFuncSetAttribute(poly_model_kernel,
                         cudaFuncAttributeMaxDynamicSharedMemorySize, SM_TOTAL);
    poly_model_kernel<<<NBLK, TPB, SM_TOTAL>>>(x, W, bias, out);
}

// round 15
// speedup vs baseline: 1.0250x; 1.0250x over previous
#include <cuda_runtime.h>
#include <cuda_bf16.h>
#include <cstdint>

// out[r] = W0 + b + sum_n x[r,n] * ( wlin[n] + D[r,n] ),
//   D[r,n] = sum_k x[r,k] * Q[k,n]   (Q upper-triangular)
// bf16 HMMA (m16n8k16), split precision: D = Xh*Bh + Xh*Bl + Xl*Bh.
//
// R15: persistent CTAs (grid=148), each handles tiles t = bid, bid+148 of
// 128 rows. B split built ONCE per CTA (overlapping tile-0 LDGs); the next
// tile's LDGs are issued before the current tile's mainloop+epilogue so
// DRAM latency hides under MMA work.

#define DIMS  64
#define BM    128
#define TPB   256
#define GRID  148
#define NTILE 256              // 32768 / 128
#define ASTR  144              // smem bytes per row (128B data + 16B pad)

#define SM_WLIN 0              // 64 fp32
#define SM_W0B  256
#define SM_AH   512
#define SM_AL   (SM_AH + BM * ASTR)
#define SM_BH   (SM_AL + BM * ASTR)
#define SM_BL   (SM_BH + DIMS * ASTR)
#define SM_TOTAL (SM_BL + DIMS * ASTR)

__device__ __forceinline__ uint32_t smem_u32(const void* p) {
    uint32_t a;
    asm("{ .reg .u64 t; cvta.to.shared.u64 t, %1; cvt.u32.u64 %0, t; }"
        : "=r"(a) : "l"(p));
    return a;
}
__device__ __forceinline__ void ldsm_x4(uint32_t& a0, uint32_t& a1,
                                        uint32_t& a2, uint32_t& a3, uint32_t addr) {
    asm volatile("ldmatrix.sync.aligned.m8n8.x4.shared.b16 {%0,%1,%2,%3}, [%4];"
                 : "=r"(a0), "=r"(a1), "=r"(a2), "=r"(a3) : "r"(addr));
}
__device__ __forceinline__ void ldsm_x2(uint32_t& b0, uint32_t& b1, uint32_t addr) {
    asm volatile("ldmatrix.sync.aligned.m8n8.x2.shared.b16 {%0,%1}, [%2];"
                 : "=r"(b0), "=r"(b1) : "r"(addr));
}
__device__ __forceinline__ void mma16816(float* c, uint32_t a0, uint32_t a1,
                                         uint32_t a2, uint32_t a3,
                                         uint32_t b0, uint32_t b1) {
    asm volatile(
        "mma.sync.aligned.m16n8k16.row.col.f32.bf16.bf16.f32 "
        "{%0,%1,%2,%3}, {%4,%5,%6,%7}, {%8,%9}, {%0,%1,%2,%3};"
        : "+f"(c[0]), "+f"(c[1]), "+f"(c[2]), "+f"(c[3])
        : "r"(a0), "r"(a1), "r"(a2), "r"(a3), "r"(b0), "r"(b1));
}

__global__ void __launch_bounds__(TPB, 1)
poly_model_kernel(const float* __restrict__ x,
                  const float* __restrict__ W,
                  const float* __restrict__ bias,
                  float* __restrict__ out)
{
    extern __shared__ char smem[];
    const uint32_t sb = smem_u32(smem);
    const int tid  = threadIdx.x;
    const int wid  = tid >> 5;
    const int lane = tid & 31;

    // ---- prefetch tile 0 LDGs (latency covered by B-build below) ----
    int t = blockIdx.x;
    const float4* xg = reinterpret_cast<const float4*>(x);
    float4 v[8];
    {
        const size_t tb = (size_t)t * BM * (DIMS / 4);
        #pragma unroll
        for (int i = 0; i < 8; i++)
            v[i] = xg[tb + tid + i * TPB];
    }

    if (tid < DIMS)
        reinterpret_cast<float*>(smem + SM_WLIN)[tid] = W[1 + tid];
    if (tid == 0)
        *reinterpret_cast<float*>(smem + SM_W0B) = W[0] + bias[0];

    // ---- B tiles ONCE per CTA: B[n][k]=Q[k][n] (k<=n else 0), bf16 hi/lo ----
    #pragma unroll
    for (int it = 0; it < 16; it++) {
        const int idx = tid + it * TPB;          // 0..4095
        const int n = idx >> 6, k = idx & 63;
        float bv = 0.0f;
        if (k <= n) {
            const int base = 1 + DIMS + k * DIMS - (k * (k - 1)) / 2;
            bv = W[base + (n - k)];
        }
        const __nv_bfloat16 h = __float2bfloat16(bv);
        const __nv_bfloat16 l = __float2bfloat16(bv - __bfloat162float(h));
        const int off = n * ASTR + k * 2;
        *reinterpret_cast<__nv_bfloat16*>(smem + SM_BH + off) = h;
        *reinterpret_cast<__nv_bfloat16*>(smem + SM_BL + off) = l;
    }

    // lane-constant fragment offsets
    const uint32_t aLane = (uint32_t)((((lane >> 3) & 1) * 8 + (lane & 7)) * ASTR
                                      + (lane >> 4) * 16);
    const uint32_t bLane = (uint32_t)((lane & 7) * ASTR + ((lane >> 3) & 1) * 16);
    const uint32_t aRow0 = (uint32_t)(wid * 16) * ASTR;
    const uint32_t aBase[3] = { sb + SM_AH, sb + SM_AH, sb + SM_AL };
    const uint32_t bBase[3] = { sb + SM_BH, sb + SM_BL, sb + SM_BH };

    const float* wlin = reinterpret_cast<const float*>(smem + SM_WLIN);

    // ---- persistent tile loop ----
    for (;;) {
        // convert prefetched tile -> smem A (bf16 hi/lo, padded rows)
        #pragma unroll
        for (int i = 0; i < 8; i++) {
            const int q   = tid + i * TPB;
            const int row = q >> 4;
            const int c4  = q & 15;

            __nv_bfloat162 h01 = __floats2bfloat162_rn(v[i].x, v[i].y);
            __nv_bfloat162 h23 = __floats2bfloat162_rn(v[i].z, v[i].w);
            const float2 f01 = __bfloat1622float2(h01);
            const float2 f23 = __bfloat1622float2(h23);
            __nv_bfloat162 l01 = __floats2bfloat162_rn(v[i].x - f01.x, v[i].y - f01.y);
            __nv_bfloat162 l23 = __floats2bfloat162_rn(v[i].z - f23.x, v[i].w - f23.y);

            const int off = row * ASTR + c4 * 8;
            uint2 hh, ll;
            hh.x = *reinterpret_cast<uint32_t*>(&h01);
            hh.y = *reinterpret_cast<uint32_t*>(&h23);
            ll.x = *reinterpret_cast<uint32_t*>(&l01);
            ll.y = *reinterpret_cast<uint32_t*>(&l23);
            *reinterpret_cast<uint2*>(smem + SM_AH + off) = hh;
            *reinterpret_cast<uint2*>(smem + SM_AL + off) = ll;
        }
        __syncthreads();

        // issue next tile's LDGs now; they fly under mainloop + epilogue
        const int tn = t + GRID;
        const bool more = (tn < NTILE);
        if (more) {
            const size_t tb = (size_t)tn * BM * (DIMS / 4);
            #pragma unroll
            for (int i = 0; i < 8; i++)
                v[i] = xg[tb + tid + i * TPB];
        }

        // accumulators init with wlin (D_init[r,c] = wlin[c])
        float acc[8][4];
        #pragma unroll
        for (int n = 0; n < 8; n++) {
            const float2 wl = *reinterpret_cast<const float2*>(
                &wlin[n * 8 + (lane & 3) * 2]);
            acc[n][0] = wl.x; acc[n][1] = wl.y;
            acc[n][2] = wl.x; acc[n][3] = wl.y;
        }

        // mainloop: warp owns 16 rows x 64 cols, 3 split-precision passes
        #pragma unroll
        for (int pass = 0; pass < 3; pass++) {
            const uint32_t ab = aBase[pass] + aRow0 + aLane;
            const uint32_t bb = bBase[pass] + bLane;
            #pragma unroll
            for (int k = 0; k < 4; k++) {
                const uint32_t kbyte = k * 32;
                uint32_t a0, a1, a2, a3;
                ldsm_x4(a0, a1, a2, a3, ab + kbyte);
                #pragma unroll
                for (int n = 0; n < 8; n++) {
                    uint32_t b0, b1;
                    ldsm_x2(b0, b1, bb + n * 8 * ASTR + kbyte);
                    mma16816(acc[n], a0, a1, a2, a3, b0, b1);
                }
            }
        }

        // epilogue: out[r] = sum_c x[c]*acc[c] + W0 + b
        const float w0b = *reinterpret_cast<const float*>(smem + SM_W0B);
        const int r0 = wid * 16 + (lane >> 2);
        const int r1 = r0 + 8;
        float p0 = 0.0f, p1 = 0.0f;
        #pragma unroll
        for (int n = 0; n < 8; n++) {
            const int c0 = n * 8 + (lane & 3) * 2;
            const int o0 = r0 * ASTR + c0 * 2;
            const int o1 = r1 * ASTR + c0 * 2;
            const float2 xh0 = __bfloat1622float2(
                *reinterpret_cast<const __nv_bfloat162*>(smem + SM_AH + o0));
            const float2 xl0 = __bfloat1622float2(
                *reinterpret_cast<const __nv_bfloat162*>(smem + SM_AL + o0));
            const float2 xh1 = __bfloat1622float2(
                *reinterpret_cast<const __nv_bfloat162*>(smem + SM_AH + o1));
            const float2 xl1 = __bfloat1622float2(
                *reinterpret_cast<const __nv_bfloat162*>(smem + SM_AL + o1));

            p0 = fmaf(xh0.x + xl0.x, acc[n][0], p0);
            p0 = fmaf(xh0.y + xl0.y, acc[n][1], p0);
            p1 = fmaf(xh1.x + xl1.x, acc[n][2], p1);
            p1 = fmaf(xh1.y + xl1.y, acc[n][3], p1);
        }
        p0 += __shfl_xor_sync(0xffffffffu, p0, 1);
        p0 += __shfl_xor_sync(0xffffffffu, p0, 2);
        p1 += __shfl_xor_sync(0xffffffffu, p1, 1);
        p1 += __shfl_xor_sync(0xffffffffu, p1, 2);
        if ((lane & 3) == 0) {
            const int gr = t * BM;
            out[gr + r0] = p0 + w0b;
            out[gr + r1] = p1 + w0b;
        }

        if (!more) break;
        t = tn;
        __syncthreads();   // epilogue smem reads done before next convert
    }
}

extern "C" void kernel_launch(void* const* d_in, const int* in_sizes, int n_in,
                              void* d_out, int out_size)
{
    const float* x    = (const float*)d_in[0];  // [32768, 64]
    const float* W    = (const float*)d_in[1];  // [2145]
    const float* bias = (const float*)d_in[2];  // [1]
    float* out = (float*)d_out;                 // [32768]

    cudaFuncSetAttribute(poly_model_kernel,
                         cudaFuncAttributeMaxDynamicSharedMemorySize, SM_TOTAL);
    poly_model_kernel<<<GRID, TPB, SM_TOTAL>>>(x, W, bias, out);
}